// round 1
// baseline (speedup 1.0000x reference)
#include <cuda_runtime.h>

// Problem shapes (fixed by the dataset)
#define B_  1024
#define V_  50000
#define E_  256
#define L_  17

// Split-K GEMM config
#define SPLITS  25
#define KCHUNK  2000          // V_ / SPLITS
#define BM      128
#define BN      128
#define BK      16
#define NSTEPS  (KCHUNK / BK) // 125

// Scratch: split-K partials [SPLITS][B][E] and the reduced embedding [B][E].
// Static __device__ arrays (no dynamic allocation allowed).
__device__ float g_scratch[SPLITS * B_ * E_];
__device__ float g_emb[B_ * E_];

// ---------------------------------------------------------------------------
// Kernel 1: split-K FP32 SGEMM. C_partial[split] = x_tile @ W_tile^T
// x: [B, V] row-major, W: [E, V] row-major  ->  both K-contiguous ("NT" GEMM).
// Block tile 128x128, BK=16, 256 threads, 8x8 per-thread microtile.
// ---------------------------------------------------------------------------
__global__ __launch_bounds__(256) void gemm_splitk_kernel(
    const float* __restrict__ x, const float* __restrict__ W)
{
    __shared__ float As[BK][BM];   // transposed: k-major
    __shared__ float Bs[BK][BN];

    const int tid   = threadIdx.x;
    const int brow  = blockIdx.x;          // 0..7   (B tiles)
    const int bcol  = blockIdx.y;          // 0..1   (E tiles)
    const int split = blockIdx.z;          // 0..24
    const int kbase = split * KCHUNK;

    // compute-thread mapping
    const int trm = tid >> 4;              // 0..15
    const int tcn = tid & 15;              // 0..15
    const int m0  = trm * 8;
    const int n0  = tcn * 8;

    // global-load mapping: tile is 128 rows x 16 k-floats = 512 float4.
    // thread handles f = tid and f = tid + 256: row = f>>2, kq4 = (f&3)*4
    int lr[2], lk[2];
#pragma unroll
    for (int i = 0; i < 2; i++) {
        const int f = tid + i * 256;
        lr[i] = f >> 2;
        lk[i] = (f & 3) * 4;
    }

    const float* xg = x + (size_t)(brow * BM) * V_ + kbase;
    const float* wg = W + (size_t)(bcol * BN) * V_ + kbase;

    float acc[8][8];
#pragma unroll
    for (int i = 0; i < 8; i++)
#pragma unroll
        for (int j = 0; j < 8; j++) acc[i][j] = 0.f;

    float4 aprf[2], bprf[2];

    // preload step 0
#pragma unroll
    for (int i = 0; i < 2; i++) {
        aprf[i] = *(const float4*)(xg + (size_t)lr[i] * V_ + lk[i]);
        bprf[i] = *(const float4*)(wg + (size_t)lr[i] * V_ + lk[i]);
    }
#pragma unroll
    for (int i = 0; i < 2; i++) {
        As[lk[i] + 0][lr[i]] = aprf[i].x;
        As[lk[i] + 1][lr[i]] = aprf[i].y;
        As[lk[i] + 2][lr[i]] = aprf[i].z;
        As[lk[i] + 3][lr[i]] = aprf[i].w;
        Bs[lk[i] + 0][lr[i]] = bprf[i].x;
        Bs[lk[i] + 1][lr[i]] = bprf[i].y;
        Bs[lk[i] + 2][lr[i]] = bprf[i].z;
        Bs[lk[i] + 3][lr[i]] = bprf[i].w;
    }
    __syncthreads();

    for (int s = 0; s < NSTEPS; ++s) {
        // prefetch next tile from global into registers (overlaps compute)
        if (s + 1 < NSTEPS) {
            const float* xs = xg + (size_t)(s + 1) * BK;
            const float* ws = wg + (size_t)(s + 1) * BK;
#pragma unroll
            for (int i = 0; i < 2; i++) {
                aprf[i] = *(const float4*)(xs + (size_t)lr[i] * V_ + lk[i]);
                bprf[i] = *(const float4*)(ws + (size_t)lr[i] * V_ + lk[i]);
            }
        }

#pragma unroll
        for (int k = 0; k < BK; k++) {
            const float4 a0 = *(const float4*)&As[k][m0];
            const float4 a1 = *(const float4*)&As[k][m0 + 4];
            const float4 b0 = *(const float4*)&Bs[k][n0];
            const float4 b1 = *(const float4*)&Bs[k][n0 + 4];
            const float av[8] = {a0.x, a0.y, a0.z, a0.w, a1.x, a1.y, a1.z, a1.w};
            const float bv[8] = {b0.x, b0.y, b0.z, b0.w, b1.x, b1.y, b1.z, b1.w};
#pragma unroll
            for (int i = 0; i < 8; i++)
#pragma unroll
                for (int j = 0; j < 8; j++)
                    acc[i][j] += av[i] * bv[j];
        }
        __syncthreads();

        if (s + 1 < NSTEPS) {
#pragma unroll
            for (int i = 0; i < 2; i++) {
                As[lk[i] + 0][lr[i]] = aprf[i].x;
                As[lk[i] + 1][lr[i]] = aprf[i].y;
                As[lk[i] + 2][lr[i]] = aprf[i].z;
                As[lk[i] + 3][lr[i]] = aprf[i].w;
                Bs[lk[i] + 0][lr[i]] = bprf[i].x;
                Bs[lk[i] + 1][lr[i]] = bprf[i].y;
                Bs[lk[i] + 2][lr[i]] = bprf[i].z;
                Bs[lk[i] + 3][lr[i]] = bprf[i].w;
            }
            __syncthreads();
        }
    }

    // epilogue: write partials (every element of g_scratch is written -> no init needed)
    float* op = g_scratch + (size_t)split * (B_ * E_)
              + (size_t)(brow * BM + m0) * E_ + (bcol * BN + n0);
#pragma unroll
    for (int i = 0; i < 8; i++) {
        float4 v0 = {acc[i][0], acc[i][1], acc[i][2], acc[i][3]};
        float4 v1 = {acc[i][4], acc[i][5], acc[i][6], acc[i][7]};
        *(float4*)(op + (size_t)i * E_)     = v0;
        *(float4*)(op + (size_t)i * E_ + 4) = v1;
    }
}

// ---------------------------------------------------------------------------
// Kernel 2: deterministic split-K reduction + bias  -> g_emb
// ---------------------------------------------------------------------------
__global__ __launch_bounds__(256) void reduce_bias_kernel(const float* __restrict__ bias)
{
    const int idx = blockIdx.x * blockDim.x + threadIdx.x;   // < B_*E_
    float s = 0.f;
#pragma unroll
    for (int sp = 0; sp < SPLITS; sp++)
        s += g_scratch[(size_t)sp * (B_ * E_) + idx];
    s += bias[idx & (E_ - 1)];
    g_emb[idx] = s;
}

// ---------------------------------------------------------------------------
// Kernel 3: per-path dots, signed sigmoid, sequential product (matches
// reference order: factors l = 0..16 left-to-right, stable sigmoid).
// One warp per batch row.
// ---------------------------------------------------------------------------
__global__ __launch_bounds__(128) void path_prod_kernel(
    const float* __restrict__ pv, const int* __restrict__ signs,
    float* __restrict__ out)
{
    const int warp = threadIdx.x >> 5;
    const int lane = threadIdx.x & 31;
    const int b    = blockIdx.x * 4 + warp;

    float e[8];
#pragma unroll
    for (int j = 0; j < 8; j++)
        e[j] = g_emb[b * E_ + lane + 32 * j];

    float prod = 1.f;
#pragma unroll 1
    for (int l = 0; l < L_; l++) {
        const float* p = pv + ((size_t)b * L_ + l) * E_;
        float d = 0.f;
#pragma unroll
        for (int j = 0; j < 8; j++)
            d += p[lane + 32 * j] * e[j];
#pragma unroll
        for (int off = 16; off; off >>= 1)
            d += __shfl_xor_sync(0xFFFFFFFFu, d, off);

        const int   sg    = signs[b * L_ + l];
        const float logit = d * (float)(2 * sg - 1);

        float sgm;
        if (logit >= 0.f) {
            sgm = 1.f / (1.f + expf(-logit));
        } else {
            const float ex = expf(logit);     // stable tail, matches jax.nn.sigmoid
            sgm = ex / (1.f + ex);
        }
        prod *= sgm;
    }
    if (lane == 0) out[b] = prod;
}

// ---------------------------------------------------------------------------
// Launch. Inputs (metadata order): x[B*V], W[E*V], b[E], path_vectors[B*L*E],
// path_signs[B*L] (int32). Output: float[B].
// ---------------------------------------------------------------------------
extern "C" void kernel_launch(void* const* d_in, const int* in_sizes, int n_in,
                              void* d_out, int out_size)
{
    const float* x     = (const float*)d_in[0];
    const float* W     = (const float*)d_in[1];
    const float* bias  = (const float*)d_in[2];
    const float* pv    = (const float*)d_in[3];
    const int*   signs = (const int*)  d_in[4];
    float*       out   = (float*)d_out;

    dim3 g1(B_ / BM, E_ / BN, SPLITS);   // (8, 2, 25) = 400 CTAs
    gemm_splitk_kernel<<<g1, 256>>>(x, W);

    reduce_bias_kernel<<<(B_ * E_) / 256, 256>>>(bias);

    path_prod_kernel<<<B_ / 4, 128>>>(pv, signs, out);
}

// round 2
// speedup vs baseline: 1.3999x; 1.3999x over previous
#include <cuda_runtime.h>

// Problem shapes (fixed by the dataset)
#define B_  1024
#define V_  50000
#define E_  256
#define L_  17

// Split-K GEMM config
#define SPLITS  25
#define KCHUNK  2000          // V_ / SPLITS
#define BM      128
#define BN      128
#define BK      16
#define NSTEPS  (KCHUNK / BK) // 125

// Scratch: split-K partials [SPLITS][B][E].
__device__ float g_scratch[SPLITS * B_ * E_];

// Packed f32x2 FMA: d.lo += a.lo*b.lo; d.hi += a.hi*b.hi  (exact fp32 FMA x2)
#define FFMA2(d, a, b) \
    asm("fma.rn.f32x2 %0, %1, %2, %0;" : "+l"(d) : "l"(a), "l"(b))

#define DUP_F32X2(d, s) \
    asm("mov.b64 %0, {%1, %1};" : "=l"(d) : "f"(s))

// ---------------------------------------------------------------------------
// Kernel 1: split-K FP32 SGEMM via packed fma.rn.f32x2.
// x: [B, V] row-major, W: [E, V] row-major -> K-contiguous NT GEMM.
// Block tile 128x128, BK=16, 256 threads, 8x8 per-thread microtile
// (stored as 8x4 packed f32x2 accumulators).
// ---------------------------------------------------------------------------
__global__ __launch_bounds__(256, 2) void gemm_splitk_kernel(
    const float* __restrict__ x, const float* __restrict__ W)
{
    __shared__ float As[BK][BM];   // k-major
    __shared__ float Bs[BK][BN];

    const int tid   = threadIdx.x;
    const int brow  = blockIdx.x;          // 0..7   (B tiles)
    const int bcol  = blockIdx.y;          // 0..1   (E tiles)
    const int split = blockIdx.z;          // 0..24
    const int kbase = split * KCHUNK;

    const int trm = tid >> 4;              // 0..15
    const int tcn = tid & 15;              // 0..15
    const int m0  = trm * 8;
    const int n0  = tcn * 8;

    // global-load mapping: tile is 128 rows x 16 k-floats = 512 float4.
    int lr[2], lk[2];
#pragma unroll
    for (int i = 0; i < 2; i++) {
        const int f = tid + i * 256;
        lr[i] = f >> 2;
        lk[i] = (f & 3) * 4;
    }

    const float* xg = x + (size_t)(brow * BM) * V_ + kbase;
    const float* wg = W + (size_t)(bcol * BN) * V_ + kbase;

    // 8x8 f32 microtile as 8x4 packed f32x2 (pairs along n)
    unsigned long long acc2[8][4];
#pragma unroll
    for (int i = 0; i < 8; i++)
#pragma unroll
        for (int j = 0; j < 4; j++) acc2[i][j] = 0ull;  // {0.f, 0.f}

    float4 aprf[2], bprf[2];

    // preload step 0
#pragma unroll
    for (int i = 0; i < 2; i++) {
        aprf[i] = *(const float4*)(xg + (size_t)lr[i] * V_ + lk[i]);
        bprf[i] = *(const float4*)(wg + (size_t)lr[i] * V_ + lk[i]);
    }
#pragma unroll
    for (int i = 0; i < 2; i++) {
        As[lk[i] + 0][lr[i]] = aprf[i].x;
        As[lk[i] + 1][lr[i]] = aprf[i].y;
        As[lk[i] + 2][lr[i]] = aprf[i].z;
        As[lk[i] + 3][lr[i]] = aprf[i].w;
        Bs[lk[i] + 0][lr[i]] = bprf[i].x;
        Bs[lk[i] + 1][lr[i]] = bprf[i].y;
        Bs[lk[i] + 2][lr[i]] = bprf[i].z;
        Bs[lk[i] + 3][lr[i]] = bprf[i].w;
    }
    __syncthreads();

    for (int s = 0; s < NSTEPS; ++s) {
        // prefetch next tile into registers (overlaps compute)
        if (s + 1 < NSTEPS) {
            const float* xs = xg + (size_t)(s + 1) * BK;
            const float* ws = wg + (size_t)(s + 1) * BK;
#pragma unroll
            for (int i = 0; i < 2; i++) {
                aprf[i] = *(const float4*)(xs + (size_t)lr[i] * V_ + lk[i]);
                bprf[i] = *(const float4*)(ws + (size_t)lr[i] * V_ + lk[i]);
            }
        }

#pragma unroll
        for (int k = 0; k < BK; k++) {
            const float4 a0 = *(const float4*)&As[k][m0];
            const float4 a1 = *(const float4*)&As[k][m0 + 4];
            // b pairs come packed for free from the 128-bit shared load
            const ulonglong2 bq0 = *(const ulonglong2*)&Bs[k][n0];
            const ulonglong2 bq1 = *(const ulonglong2*)&Bs[k][n0 + 4];
            const unsigned long long bv2[4] = {bq0.x, bq0.y, bq1.x, bq1.y};

            const float av[8] = {a0.x, a0.y, a0.z, a0.w, a1.x, a1.y, a1.z, a1.w};
            unsigned long long av2[8];
#pragma unroll
            for (int i = 0; i < 8; i++) DUP_F32X2(av2[i], av[i]);

#pragma unroll
            for (int i = 0; i < 8; i++)
#pragma unroll
                for (int j = 0; j < 4; j++)
                    FFMA2(acc2[i][j], av2[i], bv2[j]);
        }
        __syncthreads();

        if (s + 1 < NSTEPS) {
#pragma unroll
            for (int i = 0; i < 2; i++) {
                As[lk[i] + 0][lr[i]] = aprf[i].x;
                As[lk[i] + 1][lr[i]] = aprf[i].y;
                As[lk[i] + 2][lr[i]] = aprf[i].z;
                As[lk[i] + 3][lr[i]] = aprf[i].w;
                Bs[lk[i] + 0][lr[i]] = bprf[i].x;
                Bs[lk[i] + 1][lr[i]] = bprf[i].y;
                Bs[lk[i] + 2][lr[i]] = bprf[i].z;
                Bs[lk[i] + 3][lr[i]] = bprf[i].w;
            }
            __syncthreads();
        }
    }

    // epilogue: packed pairs are already in output (n-contiguous) order
    float* op = g_scratch + (size_t)split * (B_ * E_)
              + (size_t)(brow * BM + m0) * E_ + (bcol * BN + n0);
#pragma unroll
    for (int i = 0; i < 8; i++) {
        ulonglong2 v0 = {acc2[i][0], acc2[i][1]};
        ulonglong2 v1 = {acc2[i][2], acc2[i][3]};
        *(ulonglong2*)(op + (size_t)i * E_)     = v0;
        *(ulonglong2*)(op + (size_t)i * E_ + 4) = v1;
    }
}

// ---------------------------------------------------------------------------
// Kernel 2 (fused): split-K reduction + bias + per-path dots + signed sigmoid
// + sequential product. One warp per batch row; deterministic order.
// ---------------------------------------------------------------------------
__global__ __launch_bounds__(128) void path_prod_kernel(
    const float* __restrict__ bias, const float* __restrict__ pv,
    const int* __restrict__ signs, float* __restrict__ out)
{
    const int warp = threadIdx.x >> 5;
    const int lane = threadIdx.x & 31;
    const int b    = blockIdx.x * 4 + warp;

    // e[j] = bias + sum over splits (deterministic split order, matches prior rounds)
    float e[8];
#pragma unroll
    for (int j = 0; j < 8; j++) {
        const int col = lane + 32 * j;
        float s = 0.f;
#pragma unroll
        for (int sp = 0; sp < SPLITS; sp++)
            s += g_scratch[(size_t)sp * (B_ * E_) + (size_t)b * E_ + col];
        e[j] = s + bias[col];
    }

    float prod = 1.f;
#pragma unroll 1
    for (int l = 0; l < L_; l++) {
        const float* p = pv + ((size_t)b * L_ + l) * E_;
        float d = 0.f;
#pragma unroll
        for (int j = 0; j < 8; j++)
            d += p[lane + 32 * j] * e[j];
#pragma unroll
        for (int off = 16; off; off >>= 1)
            d += __shfl_xor_sync(0xFFFFFFFFu, d, off);

        const int   sg    = signs[b * L_ + l];
        const float logit = d * (float)(2 * sg - 1);

        float sgm;
        if (logit >= 0.f) {
            sgm = 1.f / (1.f + expf(-logit));
        } else {
            const float ex = expf(logit);     // stable tail, matches jax.nn.sigmoid
            sgm = ex / (1.f + ex);
        }
        prod *= sgm;
    }
    if (lane == 0) out[b] = prod;
}

// ---------------------------------------------------------------------------
// Launch. Inputs (metadata order): x[B*V], W[E*V], b[E], path_vectors[B*L*E],
// path_signs[B*L] (int32). Output: float[B].
// ---------------------------------------------------------------------------
extern "C" void kernel_launch(void* const* d_in, const int* in_sizes, int n_in,
                              void* d_out, int out_size)
{
    const float* x     = (const float*)d_in[0];
    const float* W     = (const float*)d_in[1];
    const float* bias  = (const float*)d_in[2];
    const float* pv    = (const float*)d_in[3];
    const int*   signs = (const int*)  d_in[4];
    float*       out   = (float*)d_out;

    dim3 g1(B_ / BM, E_ / BN, SPLITS);   // (8, 2, 25) = 400 CTAs
    gemm_splitk_kernel<<<g1, 256>>>(x, W);

    path_prod_kernel<<<B_ / 4, 128>>>(bias, pv, signs, out);
}